// round 13
// baseline (speedup 1.0000x reference)
#include <cuda_runtime.h>
#include <cstdint>

#define NTOK 65536
#define EDIM 256
#define NE   1024

#define OFF_ZQ   0
#define OFF_LOSS 16777216
#define OFF_IDX  16777217
#define OFF_SAMP 16842753
#define OFF_MCD  16844801
#define OFF_MCV  16844802

typedef unsigned long long ull;

static __device__ float  g_zz[NTOK];
static __device__ float  g_ee[NE];
static __device__ int    g_idx[NTOK];
static __device__ float  g_cd[NE * NE];
static __device__ float  g_z0[NTOK * EDIM];   // tf32 hi of z, layout [b][k][s]
static __device__ float  g_z1[NTOK * EDIM];   // tf32 lo of z, layout [b][k][s]
static __device__ float  g_e0T[EDIM * NE];    // tf32 hi of emb, [k][n]
static __device__ float  g_e1T[EDIM * NE];    // tf32 lo of emb, [k][n]
static __device__ double g_loss_acc;
static __device__ double g_min2_acc;
static __device__ double g_var_acc;

// ---------------------------------------------------------------------------
__device__ __forceinline__ uint32_t smem_u32(const void* p) {
    uint32_t a;
    asm("{ .reg .u64 t; cvta.to.shared.u64 t, %1; cvt.u32.u64 %0, t; }"
        : "=r"(a) : "l"(p));
    return a;
}
__device__ __forceinline__ float tf32r(float v) {
    uint32_t r;
    asm("cvt.rna.tf32.f32 %0, %1;" : "=r"(r) : "f"(v));
    return __uint_as_float(r);
}
__device__ __forceinline__ void cp_async16(uint32_t sdst, const void* gsrc) {
    asm volatile("cp.async.ca.shared.global [%0], [%1], 16;\n" ::
                 "r"(sdst), "l"(gsrc));
}
__device__ __forceinline__ void cp_commit() {
    asm volatile("cp.async.commit_group;\n");
}
__device__ __forceinline__ void cp_wait0() {
    asm volatile("cp.async.wait_group 0;\n" ::: "memory");
}
// m16n8k8 tf32 MMA (sm_80+ base ISA)
__device__ __forceinline__ void mma8(float* d, const unsigned* a,
                                     const unsigned* b) {
    asm volatile(
        "mma.sync.aligned.m16n8k8.row.col.f32.tf32.tf32.f32 "
        "{%0,%1,%2,%3},{%4,%5,%6,%7},{%8,%9},{%0,%1,%2,%3};"
        : "+f"(d[0]), "+f"(d[1]), "+f"(d[2]), "+f"(d[3])
        : "r"(a[0]), "r"(a[1]), "r"(a[2]), "r"(a[3]), "r"(b[0]), "r"(b[1]));
}

// ---------------------------------------------------------------------------
__global__ void init_kernel(float* __restrict__ out) {
    int i = blockIdx.x * blockDim.x + threadIdx.x;
    if (i < 2048) out[OFF_SAMP + i] = 0.0f;
    if (i == 0) { g_loss_acc = 0.0; g_min2_acc = 0.0; g_var_acc = 0.0; }
}

__global__ void ee_kernel(const float* __restrict__ emb) {
    int n = blockIdx.x * blockDim.x + threadIdx.x;
    if (n >= NE) return;
    const float* r = emb + (size_t)n * EDIM;
    float acc = 0.0f;
    for (int c = 0; c < EDIM; c++) { float v = r[c]; acc = fmaf(v, v, acc); }
    g_ee[n] = acc;
}

__global__ void zz_kernel(const float* __restrict__ z) {
    int t = blockIdx.x * blockDim.x + threadIdx.x;
    int b = t >> 15, s = t & 32767;
    const float* base = z + ((size_t)b << 23) + s;
    float acc = 0.0f;
#pragma unroll 8
    for (int c = 0; c < EDIM; c++) {
        float v = base[(size_t)c << 15];
        acc = fmaf(v, v, acc);
    }
    g_zz[t] = acc;
}

// elementwise tf32 split of z (keeps [b][k][s] layout)
__global__ void split_z_kernel(const float* __restrict__ z) {
    size_t i = (size_t)blockIdx.x * 256 + threadIdx.x;
    float v = z[i];
    float h = tf32r(v);
    g_z0[i] = h;
    g_z1[i] = tf32r(v - h);
}

// tf32 split of emb, transposed to [k][n]
__global__ void split_e_kernel(const float* __restrict__ emb) {
    int i = blockIdx.x * 256 + threadIdx.x;   // 262144 total
    int k = i >> 10, n = i & 1023;
    float v = emb[(size_t)n * EDIM + k];
    float h = tf32r(v);
    g_e0T[i] = h;
    g_e1T[i] = tf32r(v - h);
}

// ---------------------------------------------------------------------------
// Distance argmin: tf32 3-product mma.sync filter + exact fp32 recheck.
// CTA = 512 threads (16 warps: wy=w>>2 token group of 32, wx=w&3 code group
// of 32), 128 tokens x (8 nt tiles of 128 codes). Smem tiles [16k][132]
// padded (conflict-free fragment LDS), cp.async distance-1 double buffer.
// Per-thread per-owned-token best2 rings (d-approx) -> smem candidate lists
// -> exact sequential-fp32 recheck (same arithmetic as the R7 kernel).
#define TILEB 8448            // 16*132*4 bytes
#define STAGEB 33792          // 4 tiles
__global__ void __launch_bounds__(512, 1)
dist_kernel(const float* __restrict__ z, const float* __restrict__ emb,
            float* __restrict__ out) {
    extern __shared__ char smem[];
    float* s_ee = (float*)(smem + 67584);
    ull*   s_cand = (ull*)(smem + 71680);   // [128][32]
    uint32_t sb = smem_u32(smem);

    int tid = threadIdx.x;
    int lane = tid & 31, w = tid >> 5;
    int wy = w >> 2, wx = w & 3;
    int q = lane >> 2, c = lane & 3;
    int t0 = blockIdx.x * 128;
    int bb = t0 >> 15, s0 = t0 & 32767;
    const float* zb0 = g_z0 + ((size_t)bb << 23) + s0;
    const float* zb1 = g_z1 + ((size_t)bb << 23) + s0;

    for (int i = tid; i < 1024; i += 512) s_ee[i] = g_ee[i];

    float tz[4];
#pragma unroll
    for (int mt = 0; mt < 2; mt++)
#pragma unroll
        for (int h = 0; h < 2; h++)
            tz[mt * 2 + h] = g_zz[t0 + wy * 32 + mt * 16 + h * 8 + q];

    float bd[4][2];
    int   bn[4][2];
#pragma unroll
    for (int r = 0; r < 4; r++) {
        bd[r][0] = 3.4e38f; bd[r][1] = 3.4e38f;
        bn[r][0] = 0; bn[r][1] = 0;
    }

    int srow = tid >> 5, sch = tid & 31;   // staging: 16 rows x 32 chunks

    for (int nt = 0; nt < 8; nt++) {
        int n0 = nt * 128;
        float acc[2][4][4];
#pragma unroll
        for (int mt = 0; mt < 2; mt++)
#pragma unroll
            for (int j = 0; j < 4; j++)
#pragma unroll
                for (int r = 0; r < 4; r++) acc[mt][j][r] = 0.0f;

        // prologue stage kc=0
        {
            uint32_t d0 = sb + srow * 528 + sch * 16;
            cp_async16(d0, zb0 + ((size_t)srow << 15) + sch * 4);
            cp_async16(d0 + TILEB, zb1 + ((size_t)srow << 15) + sch * 4);
            cp_async16(d0 + 2 * TILEB, g_e0T + srow * 1024 + n0 + sch * 4);
            cp_async16(d0 + 3 * TILEB, g_e1T + srow * 1024 + n0 + sch * 4);
            cp_commit();
            cp_wait0();
        }
        __syncthreads();

        for (int kc = 0; kc < 16; kc++) {
            int buf = kc & 1;
            if (kc < 15) {
                int kg = (kc + 1) * 16 + srow;
                uint32_t d0 = sb + (buf ^ 1) * STAGEB + srow * 528 + sch * 16;
                cp_async16(d0, zb0 + ((size_t)kg << 15) + sch * 4);
                cp_async16(d0 + TILEB, zb1 + ((size_t)kg << 15) + sch * 4);
                cp_async16(d0 + 2 * TILEB, g_e0T + kg * 1024 + n0 + sch * 4);
                cp_async16(d0 + 3 * TILEB, g_e1T + kg * 1024 + n0 + sch * 4);
                cp_commit();
            }
            const unsigned* A0 = (const unsigned*)(smem + buf * STAGEB);
            const unsigned* A1 = (const unsigned*)(smem + buf * STAGEB + TILEB);
            const unsigned* B0 = (const unsigned*)(smem + buf * STAGEB + 2 * TILEB);
            const unsigned* B1 = (const unsigned*)(smem + buf * STAGEB + 3 * TILEB);
#pragma unroll
            for (int lk = 0; lk < 16; lk += 8) {
                unsigned af[2][2][4], bf[2][4][2];
#pragma unroll
                for (int mt = 0; mt < 2; mt++) {
                    int tb = wy * 32 + mt * 16;
                    af[0][mt][0] = A0[(lk + c) * 132 + tb + q];
                    af[0][mt][1] = A0[(lk + c) * 132 + tb + q + 8];
                    af[0][mt][2] = A0[(lk + c + 4) * 132 + tb + q];
                    af[0][mt][3] = A0[(lk + c + 4) * 132 + tb + q + 8];
                    af[1][mt][0] = A1[(lk + c) * 132 + tb + q];
                    af[1][mt][1] = A1[(lk + c) * 132 + tb + q + 8];
                    af[1][mt][2] = A1[(lk + c + 4) * 132 + tb + q];
                    af[1][mt][3] = A1[(lk + c + 4) * 132 + tb + q + 8];
                }
#pragma unroll
                for (int j = 0; j < 4; j++) {
                    int nb = wx * 32 + j * 8;
                    bf[0][j][0] = B0[(lk + c) * 132 + nb + q];
                    bf[0][j][1] = B0[(lk + c + 4) * 132 + nb + q];
                    bf[1][j][0] = B1[(lk + c) * 132 + nb + q];
                    bf[1][j][1] = B1[(lk + c + 4) * 132 + nb + q];
                }
#pragma unroll
                for (int mt = 0; mt < 2; mt++)
#pragma unroll
                    for (int j = 0; j < 4; j++) {
                        mma8(acc[mt][j], af[0][mt], bf[0][j]);
                        mma8(acc[mt][j], af[0][mt], bf[1][j]);
                        mma8(acc[mt][j], af[1][mt], bf[0][j]);
                    }
            }
            if (kc < 15) cp_wait0();
            __syncthreads();
        }

        // nt epilogue: d-approx + best2 ring insert
#pragma unroll
        for (int mt = 0; mt < 2; mt++)
#pragma unroll
            for (int j = 0; j < 4; j++) {
                int nb = n0 + wx * 32 + j * 8 + c * 2;
                float e0v = s_ee[nb], e1v = s_ee[nb + 1];
#pragma unroll
                for (int r = 0; r < 4; r++) {
                    int rid = mt * 2 + (r >> 1);
                    int n = nb + (r & 1);
                    float ev = (r & 1) ? e1v : e0v;
                    float dv = __fadd_rn(__fadd_rn(tz[rid], ev),
                                         __fmul_rn(-2.0f, acc[mt][j][r]));
                    if (dv < bd[rid][0]) {
                        bd[rid][1] = bd[rid][0]; bn[rid][1] = bn[rid][0];
                        bd[rid][0] = dv; bn[rid][0] = n;
                    } else if (dv < bd[rid][1]) {
                        bd[rid][1] = dv; bn[rid][1] = n;
                    }
                }
            }
    }

    // publish rings
#pragma unroll
    for (int mt = 0; mt < 2; mt++)
#pragma unroll
        for (int h = 0; h < 2; h++) {
            int m = wy * 32 + mt * 16 + h * 8 + q;
            int rid = mt * 2 + h;
            int slot = (wx * 4 + c) * 2;
            s_cand[m * 32 + slot] =
                ((ull)__float_as_uint(bd[rid][0]) << 32) | (uint32_t)bn[rid][0];
            s_cand[m * 32 + slot + 1] =
                ((ull)__float_as_uint(bd[rid][1]) << 32) | (uint32_t)bn[rid][1];
        }
    __syncthreads();

    // exact recheck (one thread per token; bit-identical R7 arithmetic)
    if (tid < 128) {
        const ull* cl = s_cand + tid * 32;
        float mind = 3.4e38f;
#pragma unroll 8
        for (int s = 0; s < 32; s++) {
            float dv = __uint_as_float((uint32_t)(cl[s] >> 32));
            if (dv < mind) mind = dv;
        }
        const float TAU = 1e-4f;
        float tzx = g_zz[t0 + tid];
        const float* zc = z + ((size_t)bb << 23) + (s0 + tid);
        ull key = ~0ull;
        for (int s = 0; s < 32; s++) {
            float dv = __uint_as_float((uint32_t)(cl[s] >> 32));
            if (dv <= mind + TAU) {
                int n = (int)(cl[s] & 0xffffffffu);
                const float* er = emb + (size_t)n * EDIM;
                float acc = 0.0f;
#pragma unroll 8
                for (int k = 0; k < EDIM; k++)
                    acc = fmaf(zc[(size_t)k << 15], er[k], acc);
                float dx = __fadd_rn(__fadd_rn(tzx, g_ee[n]),
                                     __fmul_rn(-2.0f, acc));
                ull kk = ((ull)__float_as_uint(dx) << 32) | (uint32_t)n;
                if (kk < key) key = kk;
            }
        }
        int bi = (int)(key & 0xffffffffu);
        int t = t0 + tid;
        g_idx[t] = bi;
        out[OFF_IDX + t] = (float)bi;
        out[OFF_SAMP + bi] = 1.0f;   // benign race, all write 1.0f
    }
}

// ---------------------------------------------------------------------------
__global__ void zq_kernel(const float* __restrict__ z,
                          const float* __restrict__ emb,
                          float* __restrict__ out) {
    __shared__ int sidx[32];
    __shared__ double red[256];
    int tid = threadIdx.x;
    int t0 = blockIdx.x * 32;
    int b = t0 >> 15, s0 = t0 & 32767;
    if (tid < 32) sidx[tid] = g_idx[t0 + tid];
    __syncthreads();
    size_t zbase = ((size_t)b << 23) + s0;
    double acc = 0.0;
    for (int rep = 0; rep < 32; rep++) {
        int lin = rep * 256 + tid;
        int c = lin >> 5;
        int tok = lin & 31;
        float qv = emb[(size_t)sidx[tok] * EDIM + c];
        size_t addr = zbase + ((size_t)c << 15) + tok;
        float zv = z[addr];
        out[OFF_ZQ + addr] = qv;
        float d = qv - zv;
        acc += (double)d * (double)d;
    }
    red[tid] = acc;
    __syncthreads();
    for (int s = 128; s > 0; s >>= 1) {
        if (tid < s) red[tid] += red[tid + s];
        __syncthreads();
    }
    if (tid == 0) atomicAdd(&g_loss_acc, red[0]);
}

// ---------------------------------------------------------------------------
__global__ void __launch_bounds__(256)
cd_kernel(const float* __restrict__ emb) {
    __shared__ float As[16][128];
    __shared__ float Bs[16][128];
    int tid = threadIdx.x;
    int tx = tid & 15, ty = tid >> 4;
    int i0 = blockIdx.y * 128, j0 = blockIdx.x * 128;

    float acc[8][8];
#pragma unroll
    for (int i = 0; i < 8; i++)
#pragma unroll
        for (int j = 0; j < 8; j++) acc[i][j] = 0.0f;

    for (int kc = 0; kc < 16; kc++) {
        int k0 = kc * 16;
        __syncthreads();
        {
            int n = tid & 127;
            int qb = (tid >> 7) * 2;
#pragma unroll
            for (int w2 = 0; w2 < 2; w2++) {
                int q2 = qb + w2;
                float4 v = *(const float4*)(emb + (size_t)(i0 + n) * EDIM + k0 + q2 * 4);
                As[q2 * 4 + 0][n] = v.x; As[q2 * 4 + 1][n] = v.y;
                As[q2 * 4 + 2][n] = v.z; As[q2 * 4 + 3][n] = v.w;
                float4 u = *(const float4*)(emb + (size_t)(j0 + n) * EDIM + k0 + q2 * 4);
                Bs[q2 * 4 + 0][n] = u.x; Bs[q2 * 4 + 1][n] = u.y;
                Bs[q2 * 4 + 2][n] = u.z; Bs[q2 * 4 + 3][n] = u.w;
            }
        }
        __syncthreads();
#pragma unroll
        for (int kk = 0; kk < 16; kk++) {
            float a[8], bbv[8];
            float4 a0 = *(float4*)&As[kk][ty * 8];
            float4 a1 = *(float4*)&As[kk][ty * 8 + 4];
            a[0] = a0.x; a[1] = a0.y; a[2] = a0.z; a[3] = a0.w;
            a[4] = a1.x; a[5] = a1.y; a[6] = a1.z; a[7] = a1.w;
            float4 b0 = *(float4*)&Bs[kk][tx * 8];
            float4 b1 = *(float4*)&Bs[kk][tx * 8 + 4];
            bbv[0] = b0.x; bbv[1] = b0.y; bbv[2] = b0.z; bbv[3] = b0.w;
            bbv[4] = b1.x; bbv[5] = b1.y; bbv[6] = b1.z; bbv[7] = b1.w;
#pragma unroll
            for (int i = 0; i < 8; i++)
#pragma unroll
                for (int j = 0; j < 8; j++)
                    acc[i][j] = fmaf(a[i], bbv[j], acc[i][j]);
        }
    }
#pragma unroll
    for (int i = 0; i < 8; i++) {
        int gi = i0 + ty * 8 + i;
        float ei = g_ee[gi];
#pragma unroll
        for (int j = 0; j < 8; j++) {
            int gj = j0 + tx * 8 + j;
            float d = __fadd_rn(__fadd_rn(ei, g_ee[gj]), -2.0f * acc[i][j]);
            g_cd[(size_t)gi * NE + gj] = d;
        }
    }
}

__global__ void cdstats_kernel() {
    __shared__ float  s1[256], s2[256];
    __shared__ double ds[256], dq[256];
    int r = blockIdx.x, tid = threadIdx.x;
    const float* row = g_cd + (size_t)r * NE;
    float a = 3.4e38f, b2 = 3.4e38f;
    double sm = 0.0, sq = 0.0;
    for (int j = tid; j < NE; j += 256) {
        float v = row[j];
        sm += v;
        sq += (double)v * v;
        if (v < a) { b2 = a; a = v; }
        else if (v < b2) { b2 = v; }
    }
    s1[tid] = a; s2[tid] = b2; ds[tid] = sm; dq[tid] = sq;
    __syncthreads();
    for (int s = 128; s > 0; s >>= 1) {
        if (tid < s) {
            float x1 = s1[tid], x2 = s2[tid];
            float y1 = s1[tid + s], y2 = s2[tid + s];
            s1[tid] = fminf(x1, y1);
            s2[tid] = fminf(fmaxf(x1, y1), fminf(x2, y2));
            ds[tid] += ds[tid + s];
            dq[tid] += dq[tid + s];
        }
        __syncthreads();
    }
    if (tid == 0) {
        atomicAdd(&g_min2_acc, (double)s2[0]);
        double S = ds[0], Q = dq[0];
        double var = (Q - S * S / 1024.0) / 1023.0;
        atomicAdd(&g_var_acc, var);
    }
}

__global__ void fin_kernel(float* __restrict__ out) {
    float m = (float)(g_loss_acc / 16777216.0);
    out[OFF_LOSS] = 0.2f * m + m;
    out[OFF_MCD] = (float)(g_min2_acc / 1024.0);
    out[OFF_MCV] = (float)(g_var_acc / 1024.0);
}

// ---------------------------------------------------------------------------
extern "C" void kernel_launch(void* const* d_in, const int* in_sizes, int n_in,
                              void* d_out, int out_size) {
    const float* z   = (const float*)d_in[0];
    const float* emb = (const float*)d_in[1];
    float* out = (float*)d_out;

    cudaFuncSetAttribute(dist_kernel,
                         cudaFuncAttributeMaxDynamicSharedMemorySize, 104448);

    init_kernel<<<8, 256>>>(out);
    ee_kernel<<<4, 256>>>(emb);
    zz_kernel<<<256, 256>>>(z);
    split_z_kernel<<<65536, 256>>>(z);
    split_e_kernel<<<1024, 256>>>(emb);
    dist_kernel<<<512, 512, 104448>>>(z, emb, out);
    zq_kernel<<<2048, 256>>>(z, emb, out);
    cd_kernel<<<dim3(8, 8), 256>>>(emb);
    cdstats_kernel<<<1024, 256>>>();
    fin_kernel<<<1, 1>>>(out);
}

// round 15
// speedup vs baseline: 1.4526x; 1.4526x over previous
#include <cuda_runtime.h>
#include <cstdint>

#define NTOK 65536
#define EDIM 256
#define NE   1024

#define OFF_ZQ   0
#define OFF_LOSS 16777216
#define OFF_IDX  16777217
#define OFF_SAMP 16842753
#define OFF_MCD  16844801
#define OFF_MCV  16844802

typedef unsigned long long ull;

static __device__ float  g_zz[NTOK];
static __device__ float  g_ee[NE];
static __device__ int    g_idx[NTOK];
static __device__ float  g_cd[NE * NE];
// A operand pack: [k8(32)][g(4096)][lane(32)][r(4)] tf32-rounded floats
static __device__ float  g_zA[NTOK * EDIM];
// B operand pack: [k8(32)][ng(128)][lane(32)][slot(2)]
static __device__ float  g_eB[EDIM * NE];
static __device__ double g_loss_acc;
static __device__ double g_min2_acc;
static __device__ double g_var_acc;

// ---------------------------------------------------------------------------
__device__ __forceinline__ uint32_t smem_u32(const void* p) {
    uint32_t a;
    asm("{ .reg .u64 t; cvta.to.shared.u64 t, %1; cvt.u32.u64 %0, t; }"
        : "=r"(a) : "l"(p));
    return a;
}
__device__ __forceinline__ float tf32r(float v) {
    uint32_t r;
    asm("cvt.rna.tf32.f32 %0, %1;" : "=r"(r) : "f"(v));
    return __uint_as_float(r);
}
__device__ __forceinline__ void cp_async16(uint32_t sdst, const void* gsrc) {
    asm volatile("cp.async.ca.shared.global [%0], [%1], 16;\n" ::
                 "r"(sdst), "l"(gsrc));
}
__device__ __forceinline__ void cp_commit() {
    asm volatile("cp.async.commit_group;\n");
}
__device__ __forceinline__ void cp_wait0() {
    asm volatile("cp.async.wait_group 0;\n" ::: "memory");
}
// m16n8k8 tf32 MMA (sm_80+ base ISA; ran fine on sm_103 in R13)
__device__ __forceinline__ void mma8(float* d, const unsigned* a,
                                     const unsigned* b) {
    asm volatile(
        "mma.sync.aligned.m16n8k8.row.col.f32.tf32.tf32.f32 "
        "{%0,%1,%2,%3},{%4,%5,%6,%7},{%8,%9},{%0,%1,%2,%3};"
        : "+f"(d[0]), "+f"(d[1]), "+f"(d[2]), "+f"(d[3])
        : "r"(a[0]), "r"(a[1]), "r"(a[2]), "r"(a[3]), "r"(b[0]), "r"(b[1]));
}

// ---------------------------------------------------------------------------
__global__ void init_kernel(float* __restrict__ out) {
    int i = blockIdx.x * blockDim.x + threadIdx.x;
    if (i < 2048) out[OFF_SAMP + i] = 0.0f;
    if (i == 0) { g_loss_acc = 0.0; g_min2_acc = 0.0; g_var_acc = 0.0; }
}

__global__ void ee_kernel(const float* __restrict__ emb) {
    int n = blockIdx.x * blockDim.x + threadIdx.x;
    if (n >= NE) return;
    const float* r = emb + (size_t)n * EDIM;
    float acc = 0.0f;
    for (int c = 0; c < EDIM; c++) { float v = r[c]; acc = fmaf(v, v, acc); }
    g_ee[n] = acc;
}

__global__ void zz_kernel(const float* __restrict__ z) {
    int t = blockIdx.x * blockDim.x + threadIdx.x;
    int b = t >> 15, s = t & 32767;
    const float* base = z + ((size_t)b << 23) + s;
    float acc = 0.0f;
#pragma unroll 8
    for (int c = 0; c < EDIM; c++) {
        float v = base[(size_t)c << 15];
        acc = fmaf(v, v, acc);
    }
    g_zz[t] = acc;
}

// A fragment pack: thread -> one (k8, g, lane) quad, 16B coalesced write.
// r0=(m=q,k=c) r1=(q+8,c) r2=(q,c+4) r3=(q+8,c+4)  [validated map in R13]
__global__ void pack_z_kernel(const float* __restrict__ z) {
    unsigned u = blockIdx.x * 256 + threadIdx.x;   // 4194304 total
    int lane = u & 31;
    int g = (u >> 5) & 4095;
    int k8 = u >> 17;
    int q = lane >> 2, c = lane & 3;
    int t = g * 16;
    int b = t >> 15;
    int s = (t & 32767) + q;
    const float* base = z + ((size_t)b << 23);
    size_t klo = (size_t)(k8 * 8 + c) << 15;
    size_t khi = (size_t)(k8 * 8 + c + 4) << 15;
    float4 o;
    o.x = tf32r(base[klo + s]);
    o.y = tf32r(base[klo + s + 8]);
    o.z = tf32r(base[khi + s]);
    o.w = tf32r(base[khi + s + 8]);
    *(float4*)(g_zA + (size_t)u * 4) = o;
}

// B fragment pack: thread -> one (k8, ng, lane) pair. b0=(k=c,n=q) b1=(c+4,q)
__global__ void pack_e_kernel(const float* __restrict__ emb) {
    unsigned u = blockIdx.x * 256 + threadIdx.x;   // 131072 total
    int lane = u & 31;
    int ng = (u >> 5) & 127;
    int k8 = u >> 12;
    int q = lane >> 2, c = lane & 3;
    int n = ng * 8 + q;
    int k = k8 * 8 + c;
    float2 o;
    o.x = tf32r(emb[(size_t)n * EDIM + k]);
    o.y = tf32r(emb[(size_t)n * EDIM + k + 4]);
    *(float2*)(g_eB + (size_t)u * 2) = o;
}

// ---------------------------------------------------------------------------
// Distance argmin: 1-product tf32 mma filter + exact fp32 recheck.
// CTA = 512 threads (16 warps: wy token-32-group, wx code-32-group),
// 128 tokens x 8 nt tiles of 128 codes. Pre-packed fragments -> staging is
// linear cp.async (16KB/kc), fragment loads are conflict-free LDS.128/64.
// smem 36KB -> 4 CTAs/SM (single wave). Per-thread best2 rings -> smem
// candidates -> exact sequential-fp32 recheck (bit-identical R7 arithmetic).
__global__ void __launch_bounds__(512)
dist_kernel(const float* __restrict__ z, const float* __restrict__ emb,
            float* __restrict__ out) {
    extern __shared__ char smem[];
    // [0, 32768): A/B double-buffered stages (per buf: A 8KB + B 8KB)
    // [32768, 36864): s_ee
    // s_cand aliases [0, 32768) after the mainloop
    float* s_ee = (float*)(smem + 32768);
    ull*   s_cand = (ull*)smem;
    uint32_t sb = smem_u32(smem);

    int tid = threadIdx.x;
    int lane = tid & 31, w = tid >> 5;
    int wy = w >> 2, wx = w & 3;
    int q = lane >> 2, c = lane & 3;
    int t0 = blockIdx.x * 128;
    int bb = t0 >> 15, s0 = t0 & 32767;
    int g0 = t0 >> 4;

    for (int i = tid; i < 1024; i += 512) s_ee[i] = g_ee[i];

    float tz[4];
#pragma unroll
    for (int mt = 0; mt < 2; mt++)
#pragma unroll
        for (int h = 0; h < 2; h++)
            tz[mt * 2 + h] = g_zz[t0 + wy * 32 + mt * 16 + h * 8 + q];

    float bd[4][2];
    int   bn[4][2];
#pragma unroll
    for (int r = 0; r < 4; r++) {
        bd[r][0] = 3.4e38f; bd[r][1] = 3.4e38f;
        bn[r][0] = 0; bn[r][1] = 0;
    }

    // staging: 16KB per kc = 1024 x 16B chunks; 512 threads x 2
    int u0 = tid * 2;

    for (int nt = 0; nt < 8; nt++) {
        int n0 = nt * 128;
        int ng0 = nt * 16;
        float acc[2][4][4];
#pragma unroll
        for (int mt = 0; mt < 2; mt++)
#pragma unroll
            for (int j = 0; j < 4; j++)
#pragma unroll
                for (int r = 0; r < 4; r++) acc[mt][j][r] = 0.0f;

        // ---- prologue: stage kc=0 into buf 0 ----
#pragma unroll
        for (int p = 0; p < 2; p++) {
            int u = u0 + p;
            int seg = u >> 8;           // 0,1: A halves; 2,3: B halves
            int offf = (u & 255) * 4;   // float offset
            if (seg < 2) {
                cp_async16(sb + seg * 4096 + offf * 4,
                           g_zA + ((size_t)(0 + seg) * 4096 + g0) * 128 + offf);
            } else {
                int h = seg - 2;
                cp_async16(sb + 8192 + h * 4096 + offf * 4,
                           g_eB + ((size_t)(0 + h) * 128 + ng0) * 64 + offf);
            }
        }
        cp_commit();
        cp_wait0();
        __syncthreads();

        for (int kc = 0; kc < 16; kc++) {
            int buf = kc & 1;
            if (kc < 15) {
                int kb = 2 * (kc + 1);
                uint32_t db = sb + (buf ^ 1) * 16384;
#pragma unroll
                for (int p = 0; p < 2; p++) {
                    int u = u0 + p;
                    int seg = u >> 8;
                    int offf = (u & 255) * 4;
                    if (seg < 2) {
                        cp_async16(db + seg * 4096 + offf * 4,
                                   g_zA + ((size_t)(kb + seg) * 4096 + g0) * 128 + offf);
                    } else {
                        int h = seg - 2;
                        cp_async16(db + 8192 + h * 4096 + offf * 4,
                                   g_eB + ((size_t)(kb + h) * 128 + ng0) * 64 + offf);
                    }
                }
                cp_commit();
            }
            // ---- compute: 2 k8 sub-steps, conflict-free fragment loads ----
#pragma unroll
            for (int lk8 = 0; lk8 < 2; lk8++) {
                unsigned af[2][4], bf[4][2];
                uint32_t abase = sb + buf * 16384 + lk8 * 4096 + lane * 16;
                uint32_t bbase = sb + buf * 16384 + 8192 + lk8 * 4096 + lane * 8;
#pragma unroll
                for (int mt = 0; mt < 2; mt++)
                    asm volatile("ld.shared.v4.b32 {%0,%1,%2,%3}, [%4];"
                                 : "=r"(af[mt][0]), "=r"(af[mt][1]),
                                   "=r"(af[mt][2]), "=r"(af[mt][3])
                                 : "r"(abase + (wy * 2 + mt) * 512));
#pragma unroll
                for (int j = 0; j < 4; j++)
                    asm volatile("ld.shared.v2.b32 {%0,%1}, [%2];"
                                 : "=r"(bf[j][0]), "=r"(bf[j][1])
                                 : "r"(bbase + (wx * 4 + j) * 256));
#pragma unroll
                for (int mt = 0; mt < 2; mt++)
#pragma unroll
                    for (int j = 0; j < 4; j++)
                        mma8(acc[mt][j], af[mt], bf[j]);
            }
            if (kc < 15) cp_wait0();
            __syncthreads();
        }

        // ---- nt epilogue: d-approx + best2 ring insert ----
#pragma unroll
        for (int mt = 0; mt < 2; mt++)
#pragma unroll
            for (int j = 0; j < 4; j++) {
                int nb = n0 + wx * 32 + j * 8 + c * 2;
                float e0v = s_ee[nb], e1v = s_ee[nb + 1];
#pragma unroll
                for (int r = 0; r < 4; r++) {
                    int rid = mt * 2 + (r >> 1);
                    int n = nb + (r & 1);
                    float ev = (r & 1) ? e1v : e0v;
                    float dv = __fadd_rn(__fadd_rn(tz[rid], ev),
                                         __fmul_rn(-2.0f, acc[mt][j][r]));
                    if (dv < bd[rid][0]) {
                        bd[rid][1] = bd[rid][0]; bn[rid][1] = bn[rid][0];
                        bd[rid][0] = dv; bn[rid][0] = n;
                    } else if (dv < bd[rid][1]) {
                        bd[rid][1] = dv; bn[rid][1] = n;
                    }
                }
            }
    }

    __syncthreads();   // all buffer reads done before s_cand aliases them
    // publish rings
#pragma unroll
    for (int mt = 0; mt < 2; mt++)
#pragma unroll
        for (int h = 0; h < 2; h++) {
            int m = wy * 32 + mt * 16 + h * 8 + q;
            int rid = mt * 2 + h;
            int slot = (wx * 4 + c) * 2;
            s_cand[m * 32 + slot] =
                ((ull)__float_as_uint(bd[rid][0]) << 32) | (uint32_t)bn[rid][0];
            s_cand[m * 32 + slot + 1] =
                ((ull)__float_as_uint(bd[rid][1]) << 32) | (uint32_t)bn[rid][1];
        }
    __syncthreads();

    // exact recheck (one thread per token; bit-identical R7 arithmetic)
    if (tid < 128) {
        const ull* cl = s_cand + tid * 32;
        float mind = 3.4e38f;
#pragma unroll 8
        for (int s = 0; s < 32; s++) {
            float dv = __uint_as_float((uint32_t)(cl[s] >> 32));
            if (dv < mind) mind = dv;
        }
        const float TAU = 2e-4f;
        float tzx = g_zz[t0 + tid];
        const float* zc = z + ((size_t)bb << 23) + (s0 + tid);
        ull key = ~0ull;
        for (int s = 0; s < 32; s++) {
            float dv = __uint_as_float((uint32_t)(cl[s] >> 32));
            if (dv <= mind + TAU) {
                int n = (int)(cl[s] & 0xffffffffu);
                const float* er = emb + (size_t)n * EDIM;
                float acc = 0.0f;
#pragma unroll 8
                for (int k = 0; k < EDIM; k++)
                    acc = fmaf(zc[(size_t)k << 15], er[k], acc);
                float dx = __fadd_rn(__fadd_rn(tzx, g_ee[n]),
                                     __fmul_rn(-2.0f, acc));
                ull kk = ((ull)__float_as_uint(dx) << 32) | (uint32_t)n;
                if (kk < key) key = kk;
            }
        }
        int bi = (int)(key & 0xffffffffu);
        int t = t0 + tid;
        g_idx[t] = bi;
        out[OFF_IDX + t] = (float)bi;
        out[OFF_SAMP + bi] = 1.0f;   // benign race, all write 1.0f
    }
}

// ---------------------------------------------------------------------------
__global__ void zq_kernel(const float* __restrict__ z,
                          const float* __restrict__ emb,
                          float* __restrict__ out) {
    __shared__ int sidx[32];
    __shared__ double red[256];
    int tid = threadIdx.x;
    int t0 = blockIdx.x * 32;
    int b = t0 >> 15, s0 = t0 & 32767;
    if (tid < 32) sidx[tid] = g_idx[t0 + tid];
    __syncthreads();
    size_t zbase = ((size_t)b << 23) + s0;
    double acc = 0.0;
    for (int rep = 0; rep < 32; rep++) {
        int lin = rep * 256 + tid;
        int c = lin >> 5;
        int tok = lin & 31;
        float qv = emb[(size_t)sidx[tok] * EDIM + c];
        size_t addr = zbase + ((size_t)c << 15) + tok;
        float zv = z[addr];
        out[OFF_ZQ + addr] = qv;
        float d = qv - zv;
        acc += (double)d * (double)d;
    }
    red[tid] = acc;
    __syncthreads();
    for (int s = 128; s > 0; s >>= 1) {
        if (tid < s) red[tid] += red[tid + s];
        __syncthreads();
    }
    if (tid == 0) atomicAdd(&g_loss_acc, red[0]);
}

// ---------------------------------------------------------------------------
__global__ void __launch_bounds__(256)
cd_kernel(const float* __restrict__ emb) {
    __shared__ float As[16][128];
    __shared__ float Bs[16][128];
    int tid = threadIdx.x;
    int tx = tid & 15, ty = tid >> 4;
    int i0 = blockIdx.y * 128, j0 = blockIdx.x * 128;

    float acc[8][8];
#pragma unroll
    for (int i = 0; i < 8; i++)
#pragma unroll
        for (int j = 0; j < 8; j++) acc[i][j] = 0.0f;

    for (int kc = 0; kc < 16; kc++) {
        int k0 = kc * 16;
        __syncthreads();
        {
            int n = tid & 127;
            int qb = (tid >> 7) * 2;
#pragma unroll
            for (int w2 = 0; w2 < 2; w2++) {
                int q2 = qb + w2;
                float4 v = *(const float4*)(emb + (size_t)(i0 + n) * EDIM + k0 + q2 * 4);
                As[q2 * 4 + 0][n] = v.x; As[q2 * 4 + 1][n] = v.y;
                As[q2 * 4 + 2][n] = v.z; As[q2 * 4 + 3][n] = v.w;
                float4 u = *(const float4*)(emb + (size_t)(j0 + n) * EDIM + k0 + q2 * 4);
                Bs[q2 * 4 + 0][n] = u.x; Bs[q2 * 4 + 1][n] = u.y;
                Bs[q2 * 4 + 2][n] = u.z; Bs[q2 * 4 + 3][n] = u.w;
            }
        }
        __syncthreads();
#pragma unroll
        for (int kk = 0; kk < 16; kk++) {
            float a[8], bbv[8];
            float4 a0 = *(float4*)&As[kk][ty * 8];
            float4 a1 = *(float4*)&As[kk][ty * 8 + 4];
            a[0] = a0.x; a[1] = a0.y; a[2] = a0.z; a[3] = a0.w;
            a[4] = a1.x; a[5] = a1.y; a[6] = a1.z; a[7] = a1.w;
            float4 b0 = *(float4*)&Bs[kk][tx * 8];
            float4 b1 = *(float4*)&Bs[kk][tx * 8 + 4];
            bbv[0] = b0.x; bbv[1] = b0.y; bbv[2] = b0.z; bbv[3] = b0.w;
            bbv[4] = b1.x; bbv[5] = b1.y; bbv[6] = b1.z; bbv[7] = b1.w;
#pragma unroll
            for (int i = 0; i < 8; i++)
#pragma unroll
                for (int j = 0; j < 8; j++)
                    acc[i][j] = fmaf(a[i], bbv[j], acc[i][j]);
        }
    }
#pragma unroll
    for (int i = 0; i < 8; i++) {
        int gi = i0 + ty * 8 + i;
        float ei = g_ee[gi];
#pragma unroll
        for (int j = 0; j < 8; j++) {
            int gj = j0 + tx * 8 + j;
            float d = __fadd_rn(__fadd_rn(ei, g_ee[gj]), -2.0f * acc[i][j]);
            g_cd[(size_t)gi * NE + gj] = d;
        }
    }
}

__global__ void cdstats_kernel() {
    __shared__ float  s1[256], s2[256];
    __shared__ double ds[256], dq[256];
    int r = blockIdx.x, tid = threadIdx.x;
    const float* row = g_cd + (size_t)r * NE;
    float a = 3.4e38f, b2 = 3.4e38f;
    double sm = 0.0, sq = 0.0;
    for (int j = tid; j < NE; j += 256) {
        float v = row[j];
        sm += v;
        sq += (double)v * v;
        if (v < a) { b2 = a; a = v; }
        else if (v < b2) { b2 = v; }
    }
    s1[tid] = a; s2[tid] = b2; ds[tid] = sm; dq[tid] = sq;
    __syncthreads();
    for (int s = 128; s > 0; s >>= 1) {
        if (tid < s) {
            float x1 = s1[tid], x2 = s2[tid];
            float y1 = s1[tid + s], y2 = s2[tid + s];
            s1[tid] = fminf(x1, y1);
            s2[tid] = fminf(fmaxf(x1, y1), fminf(x2, y2));
            ds[tid] += ds[tid + s];
            dq[tid] += dq[tid + s];
        }
        __syncthreads();
    }
    if (tid == 0) {
        atomicAdd(&g_min2_acc, (double)s2[0]);
        double S = ds[0], Q = dq[0];
        double var = (Q - S * S / 1024.0) / 1023.0;
        atomicAdd(&g_var_acc, var);
    }
}

__global__ void fin_kernel(float* __restrict__ out) {
    float m = (float)(g_loss_acc / 16777216.0);
    out[OFF_LOSS] = 0.2f * m + m;
    out[OFF_MCD] = (float)(g_min2_acc / 1024.0);
    out[OFF_MCV] = (float)(g_var_acc / 1024.0);
}

// ---------------------------------------------------------------------------
extern "C" void kernel_launch(void* const* d_in, const int* in_sizes, int n_in,
                              void* d_out, int out_size) {
    const float* z   = (const float*)d_in[0];
    const float* emb = (const float*)d_in[1];
    float* out = (float*)d_out;

    cudaFuncSetAttribute(dist_kernel,
                         cudaFuncAttributeMaxDynamicSharedMemorySize, 36864);

    init_kernel<<<8, 256>>>(out);
    ee_kernel<<<4, 256>>>(emb);
    zz_kernel<<<256, 256>>>(z);
    pack_z_kernel<<<16384, 256>>>(z);
    pack_e_kernel<<<512, 256>>>(emb);
    dist_kernel<<<512, 512, 36864>>>(z, emb, out);
    zq_kernel<<<2048, 256>>>(z, emb, out);
    cd_kernel<<<dim3(8, 8), 256>>>(emb);
    cdstats_kernel<<<1024, 256>>>();
    fin_kernel<<<1, 1>>>(out);
}

// round 17
// speedup vs baseline: 1.9667x; 1.3539x over previous
#include <cuda_runtime.h>
#include <cstdint>

#define NTOK 65536
#define EDIM 256
#define NE   1024

#define OFF_ZQ   0
#define OFF_LOSS 16777216
#define OFF_IDX  16777217
#define OFF_SAMP 16842753
#define OFF_MCD  16844801
#define OFF_MCV  16844802

typedef unsigned long long ull;

static __device__ float  g_zz[NTOK];
static __device__ float  g_ee[NE];
static __device__ int    g_idx[NTOK];
static __device__ float  g_cd[NE * NE];
// A operand pack: [k8(32)][g(4096)][lane(32)][r(4)] tf32-rounded floats
static __device__ float  g_zA[NTOK * EDIM];
// B operand pack: [k8(32)][ng(128)][lane(32)][slot(2)]
static __device__ float  g_eB[EDIM * NE];
static __device__ double g_loss_acc;
static __device__ double g_min2_acc;
static __device__ double g_var_acc;

// ---------------------------------------------------------------------------
__device__ __forceinline__ uint32_t smem_u32(const void* p) {
    uint32_t a;
    asm("{ .reg .u64 t; cvta.to.shared.u64 t, %1; cvt.u32.u64 %0, t; }"
        : "=r"(a) : "l"(p));
    return a;
}
__device__ __forceinline__ float tf32r(float v) {
    uint32_t r;
    asm("cvt.rna.tf32.f32 %0, %1;" : "=r"(r) : "f"(v));
    return __uint_as_float(r);
}
__device__ __forceinline__ void cp_async16(uint32_t sdst, const void* gsrc) {
    asm volatile("cp.async.ca.shared.global [%0], [%1], 16;\n" ::
                 "r"(sdst), "l"(gsrc));
}
__device__ __forceinline__ void cp_commit() {
    asm volatile("cp.async.commit_group;\n");
}
template <int N>
__device__ __forceinline__ void cp_wait() {
    asm volatile("cp.async.wait_group %0;\n" :: "n"(N) : "memory");
}
// m16n8k8 tf32 MMA (sm_80+ base ISA; validated bit-exact pipeline in R13/R15)
__device__ __forceinline__ void mma8(float* d, const unsigned* a,
                                     const unsigned* b) {
    asm volatile(
        "mma.sync.aligned.m16n8k8.row.col.f32.tf32.tf32.f32 "
        "{%0,%1,%2,%3},{%4,%5,%6,%7},{%8,%9},{%0,%1,%2,%3};"
        : "+f"(d[0]), "+f"(d[1]), "+f"(d[2]), "+f"(d[3])
        : "r"(a[0]), "r"(a[1]), "r"(a[2]), "r"(a[3]), "r"(b[0]), "r"(b[1]));
}

// stage 2 k8-slices of A (4KB) + B (8KB) into smem buffer db
__device__ __forceinline__ void stage_ab(uint32_t db, int kb, int g0, int ng0,
                                         int tid) {
#pragma unroll
    for (int p = 0; p < 3; p++) {
        int u = p * 256 + tid;
        if (p == 0) {   // A: 256 chunks of 16B
            int k8s = u >> 7, off = (u & 127) * 4;
            cp_async16(db + k8s * 2048 + off * 4,
                       g_zA + ((size_t)(kb + k8s) * 4096 + g0) * 128 + off);
        } else {        // B: 512 chunks of 16B
            int v = u - 256;
            int k8s = v >> 8, off = (v & 255) * 4;
            cp_async16(db + 4096 + k8s * 4096 + off * 4,
                       g_eB + ((size_t)(kb + k8s) * 128 + ng0) * 64 + off);
        }
    }
    cp_commit();
}

// ---------------------------------------------------------------------------
__global__ void init_kernel(float* __restrict__ out) {
    int i = blockIdx.x * blockDim.x + threadIdx.x;
    if (i < 2048) out[OFF_SAMP + i] = 0.0f;
    if (i == 0) { g_loss_acc = 0.0; g_min2_acc = 0.0; g_var_acc = 0.0; }
}

__global__ void ee_kernel(const float* __restrict__ emb) {
    int n = blockIdx.x * blockDim.x + threadIdx.x;
    if (n >= NE) return;
    const float* r = emb + (size_t)n * EDIM;
    float acc = 0.0f;
    for (int c = 0; c < EDIM; c++) { float v = r[c]; acc = fmaf(v, v, acc); }
    g_ee[n] = acc;
}

__global__ void zz_kernel(const float* __restrict__ z) {
    int t = blockIdx.x * blockDim.x + threadIdx.x;
    int b = t >> 15, s = t & 32767;
    const float* base = z + ((size_t)b << 23) + s;
    float acc = 0.0f;
#pragma unroll 8
    for (int c = 0; c < EDIM; c++) {
        float v = base[(size_t)c << 15];
        acc = fmaf(v, v, acc);
    }
    g_zz[t] = acc;
}

// A fragment pack: r0=(m=q,k=c) r1=(q+8,c) r2=(q,c+4) r3=(q+8,c+4)
__global__ void pack_z_kernel(const float* __restrict__ z) {
    unsigned u = blockIdx.x * 256 + threadIdx.x;   // 4194304 total
    int lane = u & 31;
    int g = (u >> 5) & 4095;
    int k8 = u >> 17;
    int q = lane >> 2, c = lane & 3;
    int t = g * 16;
    int b = t >> 15;
    int s = (t & 32767) + q;
    const float* base = z + ((size_t)b << 23);
    size_t klo = (size_t)(k8 * 8 + c) << 15;
    size_t khi = (size_t)(k8 * 8 + c + 4) << 15;
    float4 o;
    o.x = tf32r(base[klo + s]);
    o.y = tf32r(base[klo + s + 8]);
    o.z = tf32r(base[khi + s]);
    o.w = tf32r(base[khi + s + 8]);
    *(float4*)(g_zA + (size_t)u * 4) = o;
}

// B fragment pack: b0=(k=c,n=q) b1=(c+4,q)
__global__ void pack_e_kernel(const float* __restrict__ emb) {
    unsigned u = blockIdx.x * 256 + threadIdx.x;   // 131072 total
    int lane = u & 31;
    int ng = (u >> 5) & 127;
    int k8 = u >> 12;
    int q = lane >> 2, c = lane & 3;
    int n = ng * 8 + q;
    int k = k8 * 8 + c;
    float2 o;
    o.x = tf32r(emb[(size_t)n * EDIM + k]);
    o.y = tf32r(emb[(size_t)n * EDIM + k + 4]);
    *(float2*)(g_eB + (size_t)u * 2) = o;
}

// ---------------------------------------------------------------------------
// Distance argmin: 1-product tf32 mma filter + exact fp32 recheck.
// CTA = 256 threads (8 warps: wy in {0,1} token-32-group, wx code-32-group),
// 64 tokens x 8 nt tiles of 128 codes; 1024 CTAs. 3-stage cp.async pipeline
// (prefetch distance 2), 12KB/stage. launch_bounds(256,3) -> 3 CTAs/SM.
// Per-thread best2 rings -> smem candidates -> exact sequential-fp32 recheck
// (bit-identical R7 arithmetic; validated twice).
#define BUFB 12288
__global__ void __launch_bounds__(256, 3)
dist_kernel(const float* __restrict__ z, const float* __restrict__ emb,
            float* __restrict__ out) {
    extern __shared__ char smem[];
    // [0, 36864): 3 stage buffers; [36864, 40960): s_ee
    // s_cand (64 tok x 32 slots x 8B = 16KB) aliases [0,16384) after mainloop
    float* s_ee = (float*)(smem + 36864);
    ull*   s_cand = (ull*)smem;
    uint32_t sb = smem_u32(smem);

    int tid = threadIdx.x;
    int lane = tid & 31, w = tid >> 5;
    int wy = w >> 2, wx = w & 3;
    int q = lane >> 2, c = lane & 3;
    int t0 = blockIdx.x * 64;
    int bb = t0 >> 15, s0 = t0 & 32767;
    int g0 = t0 >> 4;

    for (int i = tid; i < 1024; i += 256) s_ee[i] = g_ee[i];

    float tz[4];
#pragma unroll
    for (int mt = 0; mt < 2; mt++)
#pragma unroll
        for (int h = 0; h < 2; h++)
            tz[mt * 2 + h] = g_zz[t0 + wy * 32 + mt * 16 + h * 8 + q];

    float bd[4][2];
    int   bn[4][2];
#pragma unroll
    for (int r = 0; r < 4; r++) {
        bd[r][0] = 3.4e38f; bd[r][1] = 3.4e38f;
        bn[r][0] = 0; bn[r][1] = 0;
    }

    for (int nt = 0; nt < 8; nt++) {
        int n0 = nt * 128;
        int ng0 = nt * 16;
        float acc[2][4][4];
#pragma unroll
        for (int mt = 0; mt < 2; mt++)
#pragma unroll
            for (int j = 0; j < 4; j++)
#pragma unroll
                for (int r = 0; r < 4; r++) acc[mt][j][r] = 0.0f;

        // ---- prologue: stage kc=0 and kc=1 ----
        stage_ab(sb + 0 * BUFB, 0, g0, ng0, tid);
        stage_ab(sb + 1 * BUFB, 2, g0, ng0, tid);
        cp_wait<1>();   // buf0 ready
        __syncthreads();

        for (int kc = 0; kc < 16; kc++) {
            int buf = kc % 3;
            // ---- distance-2 prefetch ----
            if (kc < 14)
                stage_ab(sb + ((kc + 2) % 3) * BUFB, 2 * (kc + 2), g0, ng0, tid);
            // ---- compute kc: 2 k8 sub-steps, conflict-free fragment LDS ----
#pragma unroll
            for (int lk8 = 0; lk8 < 2; lk8++) {
                unsigned af[2][4], bf[4][2];
                uint32_t abase = sb + buf * BUFB + lk8 * 2048 + lane * 16;
                uint32_t bbase = sb + buf * BUFB + 4096 + lk8 * 4096 + lane * 8;
#pragma unroll
                for (int mt = 0; mt < 2; mt++)
                    asm volatile("ld.shared.v4.b32 {%0,%1,%2,%3}, [%4];"
                                 : "=r"(af[mt][0]), "=r"(af[mt][1]),
                                   "=r"(af[mt][2]), "=r"(af[mt][3])
                                 : "r"(abase + (wy * 2 + mt) * 512));
#pragma unroll
                for (int j = 0; j < 4; j++)
                    asm volatile("ld.shared.v2.b32 {%0,%1}, [%2];"
                                 : "=r"(bf[j][0]), "=r"(bf[j][1])
                                 : "r"(bbase + (wx * 4 + j) * 256));
#pragma unroll
                for (int mt = 0; mt < 2; mt++)
#pragma unroll
                    for (int j = 0; j < 4; j++)
                        mma8(acc[mt][j], af[mt], bf[j]);
            }
            if (kc < 14)      cp_wait<1>();   // buf for kc+1 ready
            else if (kc == 14) cp_wait<0>();
            __syncthreads();
        }

        // ---- nt epilogue: d-approx + best2 ring insert ----
#pragma unroll
        for (int mt = 0; mt < 2; mt++)
#pragma unroll
            for (int j = 0; j < 4; j++) {
                int nb = n0 + wx * 32 + j * 8 + c * 2;
                float e0v = s_ee[nb], e1v = s_ee[nb + 1];
#pragma unroll
                for (int r = 0; r < 4; r++) {
                    int rid = mt * 2 + (r >> 1);
                    int n = nb + (r & 1);
                    float ev = (r & 1) ? e1v : e0v;
                    float dv = __fadd_rn(__fadd_rn(tz[rid], ev),
                                         __fmul_rn(-2.0f, acc[mt][j][r]));
                    if (dv < bd[rid][0]) {
                        bd[rid][1] = bd[rid][0]; bn[rid][1] = bn[rid][0];
                        bd[rid][0] = dv; bn[rid][0] = n;
                    } else if (dv < bd[rid][1]) {
                        bd[rid][1] = dv; bn[rid][1] = n;
                    }
                }
            }
    }

    __syncthreads();   // buffer reads done before s_cand aliases them
    // publish rings
#pragma unroll
    for (int mt = 0; mt < 2; mt++)
#pragma unroll
        for (int h = 0; h < 2; h++) {
            int m = wy * 32 + mt * 16 + h * 8 + q;
            int rid = mt * 2 + h;
            int slot = (wx * 4 + c) * 2;
            s_cand[m * 32 + slot] =
                ((ull)__float_as_uint(bd[rid][0]) << 32) | (uint32_t)bn[rid][0];
            s_cand[m * 32 + slot + 1] =
                ((ull)__float_as_uint(bd[rid][1]) << 32) | (uint32_t)bn[rid][1];
        }
    __syncthreads();

    // exact recheck (one thread per token; bit-identical R7 arithmetic)
    if (tid < 64) {
        const ull* cl = s_cand + tid * 32;
        float mind = 3.4e38f;
#pragma unroll 8
        for (int s = 0; s < 32; s++) {
            float dv = __uint_as_float((uint32_t)(cl[s] >> 32));
            if (dv < mind) mind = dv;
        }
        const float TAU = 2e-4f;
        float tzx = g_zz[t0 + tid];
        const float* zc = z + ((size_t)bb << 23) + (s0 + tid);
        ull key = ~0ull;
        for (int s = 0; s < 32; s++) {
            float dv = __uint_as_float((uint32_t)(cl[s] >> 32));
            if (dv <= mind + TAU) {
                int n = (int)(cl[s] & 0xffffffffu);
                const float* er = emb + (size_t)n * EDIM;
                float acc = 0.0f;
#pragma unroll 8
                for (int k = 0; k < EDIM; k++)
                    acc = fmaf(zc[(size_t)k << 15], er[k], acc);
                float dx = __fadd_rn(__fadd_rn(tzx, g_ee[n]),
                                     __fmul_rn(-2.0f, acc));
                ull kk = ((ull)__float_as_uint(dx) << 32) | (uint32_t)n;
                if (kk < key) key = kk;
            }
        }
        int bi = (int)(key & 0xffffffffu);
        int t = t0 + tid;
        g_idx[t] = bi;
        out[OFF_IDX + t] = (float)bi;
        out[OFF_SAMP + bi] = 1.0f;   // benign race, all write 1.0f
    }
}

// ---------------------------------------------------------------------------
__global__ void zq_kernel(const float* __restrict__ z,
                          const float* __restrict__ emb,
                          float* __restrict__ out) {
    __shared__ int sidx[32];
    __shared__ double red[256];
    int tid = threadIdx.x;
    int t0 = blockIdx.x * 32;
    int b = t0 >> 15, s0 = t0 & 32767;
    if (tid < 32) sidx[tid] = g_idx[t0 + tid];
    __syncthreads();
    size_t zbase = ((size_t)b << 23) + s0;
    double acc = 0.0;
    for (int rep = 0; rep < 32; rep++) {
        int lin = rep * 256 + tid;
        int c = lin >> 5;
        int tok = lin & 31;
        float qv = emb[(size_t)sidx[tok] * EDIM + c];
        size_t addr = zbase + ((size_t)c << 15) + tok;
        float zv = z[addr];
        out[OFF_ZQ + addr] = qv;
        float d = qv - zv;
        acc += (double)d * (double)d;
    }
    red[tid] = acc;
    __syncthreads();
    for (int s = 128; s > 0; s >>= 1) {
        if (tid < s) red[tid] += red[tid + s];
        __syncthreads();
    }
    if (tid == 0) atomicAdd(&g_loss_acc, red[0]);
}

// ---------------------------------------------------------------------------
__global__ void __launch_bounds__(256)
cd_kernel(const float* __restrict__ emb) {
    __shared__ float As[16][128];
    __shared__ float Bs[16][128];
    int tid = threadIdx.x;
    int tx = tid & 15, ty = tid >> 4;
    int i0 = blockIdx.y * 128, j0 = blockIdx.x * 128;

    float acc[8][8];
#pragma unroll
    for (int i = 0; i < 8; i++)
#pragma unroll
        for (int j = 0; j < 8; j++) acc[i][j] = 0.0f;

    for (int kc = 0; kc < 16; kc++) {
        int k0 = kc * 16;
        __syncthreads();
        {
            int n = tid & 127;
            int qb = (tid >> 7) * 2;
#pragma unroll
            for (int w2 = 0; w2 < 2; w2++) {
                int q2 = qb + w2;
                float4 v = *(const float4*)(emb + (size_t)(i0 + n) * EDIM + k0 + q2 * 4);
                As[q2 * 4 + 0][n] = v.x; As[q2 * 4 + 1][n] = v.y;
                As[q2 * 4 + 2][n] = v.z; As[q2 * 4 + 3][n] = v.w;
                float4 u = *(const float4*)(emb + (size_t)(j0 + n) * EDIM + k0 + q2 * 4);
                Bs[q2 * 4 + 0][n] = u.x; Bs[q2 * 4 + 1][n] = u.y;
                Bs[q2 * 4 + 2][n] = u.z; Bs[q2 * 4 + 3][n] = u.w;
            }
        }
        __syncthreads();
#pragma unroll
        for (int kk = 0; kk < 16; kk++) {
            float a[8], bbv[8];
            float4 a0 = *(float4*)&As[kk][ty * 8];
            float4 a1 = *(float4*)&As[kk][ty * 8 + 4];
            a[0] = a0.x; a[1] = a0.y; a[2] = a0.z; a[3] = a0.w;
            a[4] = a1.x; a[5] = a1.y; a[6] = a1.z; a[7] = a1.w;
            float4 b0 = *(float4*)&Bs[kk][tx * 8];
            float4 b1 = *(float4*)&Bs[kk][tx * 8 + 4];
            bbv[0] = b0.x; bbv[1] = b0.y; bbv[2] = b0.z; bbv[3] = b0.w;
            bbv[4] = b1.x; bbv[5] = b1.y; bbv[6] = b1.z; bbv[7] = b1.w;
#pragma unroll
            for (int i = 0; i < 8; i++)
#pragma unroll
                for (int j = 0; j < 8; j++)
                    acc[i][j] = fmaf(a[i], bbv[j], acc[i][j]);
        }
    }
#pragma unroll
    for (int i = 0; i < 8; i++) {
        int gi = i0 + ty * 8 + i;
        float ei = g_ee[gi];
#pragma unroll
        for (int j = 0; j < 8; j++) {
            int gj = j0 + tx * 8 + j;
            float d = __fadd_rn(__fadd_rn(ei, g_ee[gj]), -2.0f * acc[i][j]);
            g_cd[(size_t)gi * NE + gj] = d;
        }
    }
}

__global__ void cdstats_kernel() {
    __shared__ float  s1[256], s2[256];
    __shared__ double ds[256], dq[256];
    int r = blockIdx.x, tid = threadIdx.x;
    const float* row = g_cd + (size_t)r * NE;
    float a = 3.4e38f, b2 = 3.4e38f;
    double sm = 0.0, sq = 0.0;
    for (int j = tid; j < NE; j += 256) {
        float v = row[j];
        sm += v;
        sq += (double)v * v;
        if (v < a) { b2 = a; a = v; }
        else if (v < b2) { b2 = v; }
    }
    s1[tid] = a; s2[tid] = b2; ds[tid] = sm; dq[tid] = sq;
    __syncthreads();
    for (int s = 128; s > 0; s >>= 1) {
        if (tid < s) {
            float x1 = s1[tid], x2 = s2[tid];
            float y1 = s1[tid + s], y2 = s2[tid + s];
            s1[tid] = fminf(x1, y1);
            s2[tid] = fminf(fmaxf(x1, y1), fminf(x2, y2));
            ds[tid] += ds[tid + s];
            dq[tid] += dq[tid + s];
        }
        __syncthreads();
    }
    if (tid == 0) {
        atomicAdd(&g_min2_acc, (double)s2[0]);
        double S = ds[0], Q = dq[0];
        double var = (Q - S * S / 1024.0) / 1023.0;
        atomicAdd(&g_var_acc, var);
    }
}

__global__ void fin_kernel(float* __restrict__ out) {
    float m = (float)(g_loss_acc / 16777216.0);
    out[OFF_LOSS] = 0.2f * m + m;
    out[OFF_MCD] = (float)(g_min2_acc / 1024.0);
    out[OFF_MCV] = (float)(g_var_acc / 1024.0);
}

// ---------------------------------------------------------------------------
extern "C" void kernel_launch(void* const* d_in, const int* in_sizes, int n_in,
                              void* d_out, int out_size) {
    const float* z   = (const float*)d_in[0];
    const float* emb = (const float*)d_in[1];
    float* out = (float*)d_out;

    cudaFuncSetAttribute(dist_kernel,
                         cudaFuncAttributeMaxDynamicSharedMemorySize, 40960);

    init_kernel<<<8, 256>>>(out);
    ee_kernel<<<4, 256>>>(emb);
    zz_kernel<<<256, 256>>>(z);
    pack_z_kernel<<<16384, 256>>>(z);
    pack_e_kernel<<<512, 256>>>(emb);
    dist_kernel<<<1024, 256, 40960>>>(z, emb, out);
    zq_kernel<<<2048, 256>>>(z, emb, out);
    cd_kernel<<<dim3(8, 8), 256>>>(emb);
    cdstats_kernel<<<1024, 256>>>();
    fin_kernel<<<1, 1>>>(out);
}